// round 4
// baseline (speedup 1.0000x reference)
#include <cuda_runtime.h>

// RandFlow: depthwise 41x41 Gaussian (sigma=5) of flow = 2*noise-1, separable.
// Tap-outer sliding-window rings, 16 outputs/thread, packed fma.rn.f32x2.
// R4: deeper rings (prefetch dist 9 global / 5 smem), forced reg budget
// (launch_bounds(128,5) -> 102 regs) to kill local spills.

#define IMG_H 512
#define IMG_W 512
#define IMG_B 16

__device__ unsigned long long g_scratch[IMG_B * IMG_H * IMG_W]; // float2 as u64

__device__ constexpr float GK[41] = {
    0.00033546f, 0.00073182f, 0.00153381f, 0.00308872f, 0.00597603f,
    0.01110900f, 0.01984110f, 0.03404746f, 0.05613476f, 0.08892166f,
    0.13533528f, 0.19789871f, 0.27803730f, 0.37531110f, 0.48675226f,
    0.60653066f, 0.72614904f, 0.83527021f, 0.92311635f, 0.98019867f,
    1.00000000f,
    0.98019867f, 0.92311635f, 0.83527021f, 0.72614904f, 0.60653066f,
    0.48675226f, 0.37531110f, 0.27803730f, 0.19789871f, 0.13533528f,
    0.08892166f, 0.05613476f, 0.03404746f, 0.01984110f, 0.01110900f,
    0.00597603f, 0.00308872f, 0.00153381f, 0.00073182f, 0.00033546f
};

// fold 1/S^2 (S = 12.5326388) and (2x-1) into pass-1 load
#define SCALE_A 0.012733434f
#define SCALE_B (-0.006366717f)

__device__ __forceinline__ unsigned long long pk2(float g) {
    unsigned int u = __float_as_uint(g);   // constant-folds for literals
    return ((unsigned long long)u << 32) | (unsigned long long)u;
}
__device__ __forceinline__ void ffma2(unsigned long long& d,
                                      unsigned long long a,
                                      unsigned long long b) {
    asm("fma.rn.f32x2 %0, %1, %2, %0;" : "+l"(d) : "l"(a), "l"(b));
}

// ---------------- Pass 1: horizontal, smem row cache (skewed) --------------
// 1 warp per row, 4 rows/block. Thread: 16 consecutive w-outputs.
// Ring W1=20 -> smem prefetch distance 5 iterations (LDS lat 29 covered).
#define W1 20
__global__ void __launch_bounds__(128, 5) rf_pass1(const float2* __restrict__ in) {
    __shared__ unsigned long long s[4][592];   // 552 + skew per row
    const int warp = threadIdx.x >> 5;
    const int lane = threadIdx.x & 31;
    const int row  = blockIdx.x * 4 + warp;    // b*512 + h
    const float2* src = in + (size_t)row * IMG_W;
    unsigned long long* S = s[warp];

    // fill padded row: x in [0,552), input w = x-20, affine folded in
    for (int x = lane; x < IMG_W + 40; x += 32) {
        float vx = 0.f, vy = 0.f;
        int w = x - 20;
        if ((unsigned)w < (unsigned)IMG_W) {
            float2 t = src[w];
            vx = fmaf(t.x, SCALE_A, SCALE_B);
            vy = fmaf(t.y, SCALE_A, SCALE_B);
        }
        S[x + (x >> 4)] = ((unsigned long long)__float_as_uint(vy) << 32)
                        |  (unsigned long long)__float_as_uint(vx);
    }
    __syncwarp();

    const int base = lane * 17;     // skewed lane window base (X0 = 16*lane)
    unsigned long long win[W1], acc[16];
#pragma unroll
    for (int i = 0; i < W1; ++i) win[i] = S[base + i + (i >> 4)];
#pragma unroll
    for (int r = 0; r < 16; ++r) acc[r] = 0ull;

#pragma unroll
    for (int k = 0; k < 41; ++k) {
        const unsigned long long g = pk2(GK[k]);
#pragma unroll
        for (int r = 0; r < 16; ++r) ffma2(acc[r], win[(k + r) % W1], g);
        if (k + W1 < 56) {                     // prefetch i = k + 20
            const int i = k + W1;
            win[k % W1] = S[base + i + (i >> 4)];
        }
    }
    __syncwarp();

    // stage outputs (skewed: 17*lane + r), then coalesced global store
#pragma unroll
    for (int r = 0; r < 16; ++r) S[base + r] = acc[r];
    __syncwarp();

    unsigned long long* dst = g_scratch + (size_t)row * IMG_W;
#pragma unroll
    for (int j = 0; j < 16; ++j) {
        const int x = lane + 32 * j;
        dst[x] = S[x + (x >> 4)];
    }
}

// ---------------- Pass 2: vertical, 24-deep register window ---------------
// 128 threads = 128 consecutive w; thread: 16 consecutive h-outputs.
// Ring W2=24 -> global prefetch distance 9 iterations (~17 loads in flight).
#define W2 24
__global__ void __launch_bounds__(128, 5) rf_pass2(float2* __restrict__ out) {
    const int w  = (blockIdx.x & 3) * 128 + threadIdx.x;
    const int bh = blockIdx.x >> 2;
    const int b  = bh >> 5;
    const int h0 = (bh & 31) * 16;

    const unsigned long long* src =
        g_scratch + (size_t)b * IMG_H * IMG_W + w;

    unsigned long long win[W2], acc[16];
#pragma unroll
    for (int i = 0; i < W2; ++i) {
        const int h = h0 + i - 20;
        win[i] = ((unsigned)h < (unsigned)IMG_H) ? src[(size_t)h * IMG_W] : 0ull;
    }
#pragma unroll
    for (int r = 0; r < 16; ++r) acc[r] = 0ull;

#pragma unroll
    for (int k = 0; k < 41; ++k) {
        const unsigned long long g = pk2(GK[k]);
#pragma unroll
        for (int r = 0; r < 16; ++r) ffma2(acc[r], win[(k + r) % W2], g);
        if (k + W2 < 56) {                     // prefetch i = k + 24
            const int h = h0 + k + 4;          // = h0 + (k+24) - 20
            win[k % W2] = ((unsigned)h < (unsigned)IMG_H) ? src[(size_t)h * IMG_W]
                                                          : 0ull;
        }
    }

    unsigned long long* dst = (unsigned long long*)out
                            + ((size_t)b * IMG_H + h0) * IMG_W + w;
#pragma unroll
    for (int r = 0; r < 16; ++r) dst[(size_t)r * IMG_W] = acc[r];
}

extern "C" void kernel_launch(void* const* d_in, const int* in_sizes, int n_in,
                              void* d_out, int out_size) {
    const float2* noise = nullptr;
    for (int i = 0; i < n_in; ++i) {
        if (in_sizes[i] == IMG_B * IMG_H * IMG_W * 2) {
            noise = (const float2*)d_in[i];
            break;
        }
    }
    if (!noise) noise = (const float2*)d_in[n_in - 1];

    rf_pass1<<<IMG_B * IMG_H / 4, 128>>>(noise);
    rf_pass2<<<IMG_B * (IMG_H / 16) * (IMG_W / 128), 128>>>((float2*)d_out);
}

// round 5
// speedup vs baseline: 1.2088x; 1.2088x over previous
#include <cuda_runtime.h>

// RandFlow: depthwise 41x41 Gaussian (sigma=5) of flow = 2*noise-1, separable.
// Pass1: horizontal, 8 out/thread, ring W=12, high occupancy (~55 regs).
// Pass2: vertical, 16 out/thread, ring W=24 (L2-bandwidth optimal).
// Packed fma.rn.f32x2 everywhere; taps are compile-time literals.

#define IMG_H 512
#define IMG_W 512
#define IMG_B 16

__device__ unsigned long long g_scratch[IMG_B * IMG_H * IMG_W]; // float2 as u64

__device__ constexpr float GK[41] = {
    0.00033546f, 0.00073182f, 0.00153381f, 0.00308872f, 0.00597603f,
    0.01110900f, 0.01984110f, 0.03404746f, 0.05613476f, 0.08892166f,
    0.13533528f, 0.19789871f, 0.27803730f, 0.37531110f, 0.48675226f,
    0.60653066f, 0.72614904f, 0.83527021f, 0.92311635f, 0.98019867f,
    1.00000000f,
    0.98019867f, 0.92311635f, 0.83527021f, 0.72614904f, 0.60653066f,
    0.48675226f, 0.37531110f, 0.27803730f, 0.19789871f, 0.13533528f,
    0.08892166f, 0.05613476f, 0.03404746f, 0.01984110f, 0.01110900f,
    0.00597603f, 0.00308872f, 0.00153381f, 0.00073182f, 0.00033546f
};

// fold 1/S^2 (S = 12.5326388) and (2x-1) into pass-1 load
#define SCALE_A 0.012733434f
#define SCALE_B (-0.006366717f)

__device__ __forceinline__ unsigned long long pk2(float g) {
    unsigned int u = __float_as_uint(g);   // constant-folds for literals
    return ((unsigned long long)u << 32) | (unsigned long long)u;
}
__device__ __forceinline__ void ffma2(unsigned long long& d,
                                      unsigned long long a,
                                      unsigned long long b) {
    asm("fma.rn.f32x2 %0, %1, %2, %0;" : "+l"(d) : "l"(a), "l"(b));
}

// skew: f(x) = x + (x>>3); for x = 8t+i: f = 9t + i + (i>>3) (compile-time offs)
#define SKB 624   // per-row skewed size: f(551)=619

// ---------------- Pass 1: horizontal, 8 out/thread, ring W1=12 -------------
// 64 threads per row, 2 rows per block (128 thr). Grid = 16*512/2 = 4096.
#define W1 12
__global__ void __launch_bounds__(128) rf_pass1(const float2* __restrict__ in) {
    __shared__ unsigned long long s[2][SKB];
    const int half = threadIdx.x >> 6;         // which row in block
    const int t    = threadIdx.x & 63;         // thread within row
    const int row  = blockIdx.x * 2 + half;    // b*512 + h
    const float2* src = in + (size_t)row * IMG_W;
    unsigned long long* S = s[half];

    // fill padded row: x in [0,552), input w = x-20, affine folded
    for (int x = t; x < IMG_W + 40; x += 64) {
        float vx = 0.f, vy = 0.f;
        int w = x - 20;
        if ((unsigned)w < (unsigned)IMG_W) {
            float2 v = src[w];
            vx = fmaf(v.x, SCALE_A, SCALE_B);
            vy = fmaf(v.y, SCALE_A, SCALE_B);
        }
        S[x + (x >> 3)] = ((unsigned long long)__float_as_uint(vy) << 32)
                        |  (unsigned long long)__float_as_uint(vx);
    }
    __syncthreads();

    const int base = t * 9;                    // skewed base (w0 = 8t)
    unsigned long long win[W1], acc[8];
#pragma unroll
    for (int i = 0; i < W1; ++i) win[i] = S[base + i + (i >> 3)];
#pragma unroll
    for (int r = 0; r < 8; ++r) acc[r] = 0ull;

#pragma unroll
    for (int k = 0; k < 41; ++k) {
        const unsigned long long g = pk2(GK[k]);
#pragma unroll
        for (int r = 0; r < 8; ++r) ffma2(acc[r], win[(k + r) % W1], g);
        if (k < 37) {                          // prefetch i = k + 12 (max 48)
            const int i = k + W1;
            win[k % W1] = S[base + i + (i >> 3)];
        }
    }

    // direct vectorized store: 8 consecutive u64 = 4x 16B, coalesced per warp
    ulonglong2* dst = reinterpret_cast<ulonglong2*>(
        g_scratch + (size_t)row * IMG_W + t * 8);
#pragma unroll
    for (int j = 0; j < 4; ++j)
        dst[j] = make_ulonglong2(acc[2 * j], acc[2 * j + 1]);
}

// ---------------- Pass 2: vertical, 16 out/thread, ring W2=24 --------------
#define W2 24
__global__ void __launch_bounds__(128, 5) rf_pass2(float2* __restrict__ out) {
    const int w  = (blockIdx.x & 3) * 128 + threadIdx.x;
    const int bh = blockIdx.x >> 2;
    const int b  = bh >> 5;
    const int h0 = (bh & 31) * 16;

    const unsigned long long* src =
        g_scratch + (size_t)b * IMG_H * IMG_W + w;

    unsigned long long win[W2], acc[16];
#pragma unroll
    for (int i = 0; i < W2; ++i) {
        const int h = h0 + i - 20;
        win[i] = ((unsigned)h < (unsigned)IMG_H) ? src[(size_t)h * IMG_W] : 0ull;
    }
#pragma unroll
    for (int r = 0; r < 16; ++r) acc[r] = 0ull;

#pragma unroll
    for (int k = 0; k < 41; ++k) {
        const unsigned long long g = pk2(GK[k]);
#pragma unroll
        for (int r = 0; r < 16; ++r) ffma2(acc[r], win[(k + r) % W2], g);
        if (k < 32) {                          // prefetch i = k + 24
            const int h = h0 + k + 4;
            win[k % W2] = ((unsigned)h < (unsigned)IMG_H) ? src[(size_t)h * IMG_W]
                                                          : 0ull;
        }
    }

    unsigned long long* dst = (unsigned long long*)out
                            + ((size_t)b * IMG_H + h0) * IMG_W + w;
#pragma unroll
    for (int r = 0; r < 16; ++r) dst[(size_t)r * IMG_W] = acc[r];
}

extern "C" void kernel_launch(void* const* d_in, const int* in_sizes, int n_in,
                              void* d_out, int out_size) {
    const float2* noise = nullptr;
    for (int i = 0; i < n_in; ++i) {
        if (in_sizes[i] == IMG_B * IMG_H * IMG_W * 2) {
            noise = (const float2*)d_in[i];
            break;
        }
    }
    if (!noise) noise = (const float2*)d_in[n_in - 1];

    rf_pass1<<<IMG_B * IMG_H / 2, 128>>>(noise);
    rf_pass2<<<IMG_B * (IMG_H / 16) * (IMG_W / 128), 128>>>((float2*)d_out);
}